// round 10
// baseline (speedup 1.0000x reference)
#include <cuda_runtime.h>
#include <cuda_fp16.h>
#include <cstdint>

#define B_  16
#define C_  256
#define M_  4096
#define NSf 65536.0f
#define KD  16
#define UD  4
#define UK  64
#define UV  1024
#define VD  256
#define EPSBN 1e-5f

// ---------------- scratch ----------------
__device__ float  g_G[C_ * C_];
__device__ float  g_s[C_];
__device__ float  g_qf[1056];
__device__ __half g_Wh[80 * C_];          // fp16 weights (Q BN-folded rows 0-15, K rows 16-79)
__device__ float  g_bqk[80];
__device__ float  g_WvEff[UV * C_];
__device__ float  g_cb[VD];
__device__ float  g_Q[B_ * KD * M_];
__device__ float  g_P[B_ * UK * M_];      // fp32 K logits
__device__ __half g_Ph[B_ * UK * M_];     // fp16 softmax weights
__device__ float  g_T[B_ * UK * C_];
__device__ float  g_ctx[B_ * KD * VD];
__device__ __half g_xh[B_ * C_ * M_];     // x as fp16 (all GEMMs)

// ---------------- helpers ----------------
__device__ __forceinline__ void mma16h(float c[4], const unsigned a[4], const unsigned b[2]) {
    asm volatile("mma.sync.aligned.m16n8k16.row.col.f32.f16.f16.f32 "
                 "{%0,%1,%2,%3}, {%4,%5,%6,%7}, {%8,%9}, {%0,%1,%2,%3};"
                 : "+f"(c[0]), "+f"(c[1]), "+f"(c[2]), "+f"(c[3])
                 : "r"(a[0]), "r"(a[1]), "r"(a[2]), "r"(a[3]), "r"(b[0]), "r"(b[1]));
}
__device__ __forceinline__ unsigned sptr(const void* p) {
    return (unsigned)__cvta_generic_to_shared(p);
}
__device__ __forceinline__ void ldsm4(unsigned d[4], unsigned addr) {
    asm volatile("ldmatrix.sync.aligned.m8n8.x4.shared.b16 {%0,%1,%2,%3}, [%4];"
                 : "=r"(d[0]), "=r"(d[1]), "=r"(d[2]), "=r"(d[3]) : "r"(addr));
}
__device__ __forceinline__ void cpa16(unsigned saddr, const void* g) {
    asm volatile("cp.async.cg.shared.global [%0], [%1], 16;" :: "r"(saddr), "l"(g));
}
__device__ __forceinline__ void cpcommit() { asm volatile("cp.async.commit_group;"); }
__device__ __forceinline__ void cpwait1() { asm volatile("cp.async.wait_group 1;"); }

__device__ __forceinline__ unsigned a_addr(unsigned base, int R0, int kb, int lane) {
    int row = R0 + (((lane >> 3) & 1) << 3) + (lane & 7);
    int ch  = kb * 2 + (lane >> 4);
    return base + row * 128 + ((ch ^ (row & 7)) << 4);
}
__device__ __forceinline__ unsigned b_addr(unsigned base, int N0, int kb, int lane) {
    int row = N0 + ((lane >> 4) << 3) + (lane & 7);
    int ch  = kb * 2 + ((lane >> 3) & 1);
    return base + row * 128 + ((ch ^ (row & 7)) << 4);
}
__device__ __forceinline__ float2 hpair(unsigned u) {
    __half2 h = *reinterpret_cast<__half2*>(&u);
    return __half22float2(h);
}
__device__ __forceinline__ unsigned h2bits(__half2 h) {
    return *reinterpret_cast<unsigned*>(&h);
}

// ---------------- kx: zero scratch + convert x -> fp16 ----------------
__global__ __launch_bounds__(256) void kx_cvt(const float4* __restrict__ x4) {
    const size_t gs = (size_t)gridDim.x * blockDim.x;
    const size_t i0 = (size_t)blockIdx.x * blockDim.x + threadIdx.x;
    for (size_t j = i0; j < C_ * C_; j += gs) g_G[j] = 0.f;
    for (size_t j = i0; j < C_; j += gs) { g_s[j] = 0.f; g_cb[j] = 0.f; }
    for (size_t j = i0; j < 1056; j += gs) g_qf[j] = 0.f;
    for (size_t j = i0; j < (size_t)B_ * UK * C_; j += gs) g_T[j] = 0.f;
    for (size_t j = i0; j < (size_t)B_ * KD * VD; j += gs) g_ctx[j] = 0.f;
    uint2* o2 = (uint2*)g_xh;
    const size_t n4 = (size_t)B_ * C_ * M_ / 4;
    for (size_t i = i0; i < n4; i += gs) {
        float4 v = x4[i];
        o2[i] = make_uint2(h2bits(__floats2half2_rn(v.x, v.y)),
                           h2bits(__floats2half2_rn(v.z, v.w)));
    }
}

// ---------------- k1: Gram G = X X^T (fp16 mma m16n8k16) ----------------
// grid (3 sym tiles, B_, 4 k-splits of 1024), block 256 (8 warps 2x4).
__global__ __launch_bounds__(256, 2) void k1_gram() {
    extern __shared__ float smem[];
    const int t3 = blockIdx.x;
    const int ti = (t3 == 1) ? 1 : 0, tj = (t3 == 0) ? 0 : 1;
    const int b = blockIdx.y, kz = blockIdx.z;
    const int tid = threadIdx.x, lane = tid & 31, warp = tid >> 5;
    const int wm = warp >> 2, wn = warp & 3;
    const bool diag = (ti == tj);
    const __half* Ag = g_xh + (size_t)b * C_ * M_ + (size_t)(ti * 128) * M_ + kz * 1024;
    const __half* Bg = g_xh + (size_t)b * C_ * M_ + (size_t)(tj * 128) * M_ + kz * 1024;
    const unsigned s0 = sptr(smem);
    const int NC = 16;

    float acc[4][4][4];
#pragma unroll
    for (int i = 0; i < 4; i++)
#pragma unroll
        for (int j = 0; j < 4; j++)
#pragma unroll
            for (int r = 0; r < 4; r++) acc[i][j][r] = 0.f;
    float rsum[4] = {0.f, 0.f, 0.f, 0.f};

    auto stage = [&](int c, int s) {
        const __half* As = Ag + c * 64;
        unsigned ab = s0 + s * 32768u;
#pragma unroll
        for (int it = 0; it < 4; it++) {
            int id = tid + it * 256;
            int r = id >> 3, ch = id & 7;
            unsigned sw = (unsigned)(r * 128 + ((ch ^ (r & 7)) << 4));
            cpa16(ab + sw, As + (size_t)r * M_ + ch * 8);
        }
        if (!diag) {
            const __half* Bs = Bg + c * 64;
            unsigned bb = ab + 16384u;
#pragma unroll
            for (int it = 0; it < 4; it++) {
                int id = tid + it * 256;
                int r = id >> 3, ch = id & 7;
                unsigned sw = (unsigned)(r * 128 + ((ch ^ (r & 7)) << 4));
                cpa16(bb + sw, Bs + (size_t)r * M_ + ch * 8);
            }
        }
    };

    stage(0, 0); cpcommit();
    stage(1, 1); cpcommit();

    for (int i = 0; i < NC; i++) {
        cpwait1(); __syncthreads();
        int s = i % 3;
        unsigned ab = s0 + s * 32768u;
        unsigned bb = diag ? ab : (ab + 16384u);
#pragma unroll
        for (int kb = 0; kb < 4; kb++) {
            unsigned af[4][4], bf[2][4];
#pragma unroll
            for (int mf = 0; mf < 4; mf++)
                ldsm4(af[mf], a_addr(ab, wm * 64 + mf * 16, kb, lane));
#pragma unroll
            for (int p = 0; p < 2; p++) {
                ldsm4(bf[p], b_addr(bb, wn * 32 + p * 16, kb, lane));
                if (diag && wm == 0) {
                    float2 v0 = hpair(bf[p][0]), v1 = hpair(bf[p][1]);
                    float2 v2 = hpair(bf[p][2]), v3 = hpair(bf[p][3]);
                    rsum[p * 2 + 0] += v0.x + v0.y + v1.x + v1.y;
                    rsum[p * 2 + 1] += v2.x + v2.y + v3.x + v3.y;
                }
            }
#pragma unroll
            for (int mf = 0; mf < 4; mf++)
#pragma unroll
                for (int p = 0; p < 2; p++) {
                    mma16h(acc[mf][p * 2 + 0], af[mf], &bf[p][0]);
                    mma16h(acc[mf][p * 2 + 1], af[mf], &bf[p][2]);
                }
        }
        if (i + 2 < NC) stage(i + 2, (i + 2) % 3);
        cpcommit();
    }

    const int g = lane >> 2, t = lane & 3;
#pragma unroll
    for (int mf = 0; mf < 4; mf++) {
        int row = ti * 128 + wm * 64 + mf * 16 + g;
#pragma unroll
        for (int nf = 0; nf < 4; nf++) {
            int col = tj * 128 + wn * 32 + nf * 8 + 2 * t;
            atomicAdd(&g_G[row * C_ + col],           acc[mf][nf][0]);
            atomicAdd(&g_G[row * C_ + col + 1],       acc[mf][nf][1]);
            atomicAdd(&g_G[(row + 8) * C_ + col],     acc[mf][nf][2]);
            atomicAdd(&g_G[(row + 8) * C_ + col + 1], acc[mf][nf][3]);
            if (!diag) {
                atomicAdd(&g_G[col * C_ + row],           acc[mf][nf][0]);
                atomicAdd(&g_G[(col + 1) * C_ + row],     acc[mf][nf][1]);
                atomicAdd(&g_G[col * C_ + row + 8],       acc[mf][nf][2]);
                atomicAdd(&g_G[(col + 1) * C_ + row + 8], acc[mf][nf][3]);
            }
        }
    }
    if (diag && wm == 0) {
#pragma unroll
        for (int sl = 0; sl < 4; sl++) {
            float v = rsum[sl];
            v += __shfl_down_sync(0xffffffffu, v, 2, 4);
            v += __shfl_down_sync(0xffffffffu, v, 1, 4);
            if ((lane & 3) == 0) {
                int n = tj * 128 + wn * 32 + (sl >> 1) * 16 + (sl & 1) * 8 + (lane >> 2);
                atomicAdd(&g_s[n], v);
            }
        }
    }
}

// ---------------- k2a: partial quadratic forms (8-way r-split) ----------
__global__ __launch_bounds__(256) void k2a_qf(const float* __restrict__ Wq,
                                              const float* __restrict__ Wv) {
    __shared__ float wT[C_][20];
    __shared__ float qfs[16];
    const int g = blockIdx.x, rz = blockIdx.y;
    const int tid = threadIdx.x, lane = tid & 31;
    const float* Wsrc = (g == 0) ? Wq : (Wv + (size_t)(g - 1) * 16 * C_);

#pragma unroll
    for (int i = 0; i < 16; i++) wT[tid][i] = Wsrc[i * C_ + tid];
    if (tid < 16) qfs[tid] = 0.f;
    __syncthreads();

    float inner[16];
#pragma unroll
    for (int ch = 0; ch < 16; ch++) inner[ch] = 0.f;
    const int r0 = rz * 32;
#pragma unroll 8
    for (int r = r0; r < r0 + 32; r++) {
        float gg = g_G[r * C_ + tid];
        float4 w0 = *(const float4*)&wT[r][0];
        float4 w1 = *(const float4*)&wT[r][4];
        float4 w2 = *(const float4*)&wT[r][8];
        float4 w3 = *(const float4*)&wT[r][12];
        inner[0]  += w0.x * gg; inner[1]  += w0.y * gg;
        inner[2]  += w0.z * gg; inner[3]  += w0.w * gg;
        inner[4]  += w1.x * gg; inner[5]  += w1.y * gg;
        inner[6]  += w1.z * gg; inner[7]  += w1.w * gg;
        inner[8]  += w2.x * gg; inner[9]  += w2.y * gg;
        inner[10] += w2.z * gg; inner[11] += w2.w * gg;
        inner[12] += w3.x * gg; inner[13] += w3.y * gg;
        inner[14] += w3.z * gg; inner[15] += w3.w * gg;
    }
    float4 m0 = *(const float4*)&wT[tid][0];
    float4 m1 = *(const float4*)&wT[tid][4];
    float4 m2 = *(const float4*)&wT[tid][8];
    float4 m3 = *(const float4*)&wT[tid][12];
    float wc[16] = {m0.x, m0.y, m0.z, m0.w, m1.x, m1.y, m1.z, m1.w,
                    m2.x, m2.y, m2.z, m2.w, m3.x, m3.y, m3.z, m3.w};
#pragma unroll
    for (int ch = 0; ch < 16; ch++) {
        float vq = inner[ch] * wc[ch];
#pragma unroll
        for (int o = 16; o > 0; o >>= 1)
            vq += __shfl_down_sync(0xffffffffu, vq, o);
        if (lane == 0) atomicAdd(&qfs[ch], vq);
    }
    __syncthreads();
    if (tid < 16) atomicAdd(&g_qf[g * 16 + tid], qfs[tid]);
}

// ---------------- k2b: BN folding + fp16 weight writes + Wk copy ----------
__global__ __launch_bounds__(256) void k2b_fold(
    const float* __restrict__ Wq, const float* __restrict__ bq,
    const float* __restrict__ Wk, const float* __restrict__ bk,
    const float* __restrict__ Wv, const float* __restrict__ bv,
    const float* __restrict__ gq, const float* __restrict__ btq,
    const float* __restrict__ gv, const float* __restrict__ btv) {
    const int blk = blockIdx.x, tid = threadIdx.x;

    if (blk >= 65) {
        int base = (blk - 65) * 16;
#pragma unroll
        for (int i = 0; i < 16; i++)
            g_Wh[(16 + base + i) * C_ + tid] = __float2half(Wk[(base + i) * C_ + tid]);
        if (tid < 16) g_bqk[16 + base + tid] = bk[base + tid];
        return;
    }

    __shared__ float w[16][C_];
    __shared__ float dss[16], alph[16];
    const bool isQ = (blk == 0);
    const float* Wsrc = isQ ? Wq : (Wv + (size_t)(blk - 1) * 16 * C_);
#pragma unroll
    for (int i = 0; i < 16; i++) w[i][tid] = Wsrc[i * C_ + tid];
    if (tid < 16) dss[tid] = 0.f;
    __syncthreads();

    const float sc = g_s[tid];
    const int lane = tid & 31;
#pragma unroll
    for (int ch = 0; ch < 16; ch++) {
        float vd = w[ch][tid] * sc;
#pragma unroll
        for (int o = 16; o > 0; o >>= 1)
            vd += __shfl_down_sync(0xffffffffu, vd, o);
        if (lane == 0) atomicAdd(&dss[ch], vd);
    }
    __syncthreads();

    if (tid < 16) {
        int ch = tid;
        float bias, gamma, beta;
        if (isQ) { bias = bq[ch]; gamma = gq[ch]; beta = btq[ch]; }
        else {
            int gch = (blk - 1) * 16 + ch;
            bias = bv[gch]; gamma = gv[gch]; beta = btv[gch];
        }
        float dsv  = dss[ch];
        float qfv  = g_qf[blk * 16 + ch];
        float mean = dsv / NSf + bias;
        float e2   = (qfv + 2.f * bias * dsv) / NSf + bias * bias;
        float var  = e2 - mean * mean;
        float a    = gamma * rsqrtf(var + EPSBN);
        alph[ch]   = a;
        float be   = beta + a * (bias - mean);
        if (isQ) g_bqk[ch] = be;
        else {
            int gch = (blk - 1) * 16 + ch;
            atomicAdd(&g_cb[gch & (VD - 1)], be);
        }
    }
    __syncthreads();
#pragma unroll
    for (int i = 0; i < 16; i++) {
        float val = alph[i] * w[i][tid];
        if (isQ) g_Wh[i * C_ + tid] = __float2half(val);
        else     g_WvEff[((size_t)(blk - 1) * 16 + i) * C_ + tid] = val;
    }
}

// ---------------- k3: fused Q+K GEMM (fp16 mma) ----------------
// out[80, 4096] per b. grid (32 px-tiles of 128, B_). NC=4 chunks of 64 ch.
__global__ __launch_bounds__(256, 2) void k3_qk() {
    extern __shared__ float smem[];
    const int mt = blockIdx.x, b = blockIdx.y;
    const int tid = threadIdx.x, lane = tid & 31, warp = tid >> 5;
    const unsigned s0 = sptr(smem);
    const int NC = 4;

    float acc[5][2][4];
#pragma unroll
    for (int i = 0; i < 5; i++)
#pragma unroll
        for (int j = 0; j < 2; j++)
#pragma unroll
            for (int r = 0; r < 4; r++) acc[i][j][r] = 0.f;

    auto stage = [&](int c, int s) {
        unsigned ab = s0 + s * 26624u;
        // A: Wh 80 rows x 8 octs of the 64-ch chunk
#pragma unroll
        for (int it = 0; it < 3; it++) {
            int id = tid + it * 256;
            if (id < 640) {
                int r = id >> 3, ch = id & 7;
                cpa16(ab + r * 128 + ((ch ^ (r & 7)) << 4),
                      g_Wh + r * C_ + c * 64 + ch * 8);
            }
        }
        // B: transpose-stage x(fp16) -> [pixel][channel]
        const __half* xc = g_xh + (size_t)b * C_ * M_ + (size_t)(c * 64) * M_ + mt * 128;
        char* bbuf = (char*)smem + s * 26624 + 10240;
#pragma unroll
        for (int it = 0; it < 2; it++) {
            int id = tid + it * 256;           // 0..511
            int pp = id & 63;                  // pixel pair index
            int oct = id >> 6;                 // 0..7
            unsigned lo[4], hi[4];
#pragma unroll
            for (int j = 0; j < 4; j++) {
                unsigned va = *(const unsigned*)(xc + (size_t)(oct * 8 + 2 * j) * M_ + 2 * pp);
                unsigned vb = *(const unsigned*)(xc + (size_t)(oct * 8 + 2 * j + 1) * M_ + 2 * pp);
                lo[j] = __byte_perm(va, vb, 0x5410);
                hi[j] = __byte_perm(va, vb, 0x7632);
            }
            int p0 = 2 * pp, p1 = 2 * pp + 1;
            *(uint4*)(bbuf + p0 * 128 + ((oct ^ (p0 & 7)) << 4)) = make_uint4(lo[0], lo[1], lo[2], lo[3]);
            *(uint4*)(bbuf + p1 * 128 + ((oct ^ (p1 & 7)) << 4)) = make_uint4(hi[0], hi[1], hi[2], hi[3]);
        }
    };

    stage(0, 0); cpcommit();
    stage(1, 1); cpcommit();

    for (int i = 0; i < NC; i++) {
        cpwait1(); __syncthreads();
        int s = i % 3;
        unsigned ab = s0 + s * 26624u, bb = ab + 10240u;
#pragma unroll
        for (int kb = 0; kb < 4; kb++) {
            unsigned af[5][4], bf[4];
#pragma unroll
            for (int mf = 0; mf < 5; mf++)
                ldsm4(af[mf], a_addr(ab, mf * 16, kb, lane));
            ldsm4(bf, b_addr(bb, warp * 16, kb, lane));
#pragma unroll
            for (int mf = 0; mf < 5; mf++) {
                mma16h(acc[mf][0], af[mf], &bf[0]);
                mma16h(acc[mf][1], af[mf], &bf[2]);
            }
        }
        if (i + 2 < NC) stage(i + 2, (i + 2) % 3);
        cpcommit();
    }

    const int g = lane >> 2, t = lane & 3;
#pragma unroll
    for (int mf = 0; mf < 5; mf++) {
#pragma unroll
        for (int nf = 0; nf < 2; nf++) {
            int col = mt * 128 + warp * 16 + nf * 8 + 2 * t;
#pragma unroll
            for (int h = 0; h < 2; h++) {
                int row = mf * 16 + g + h * 8;
                float bias = g_bqk[row];
                float2 v = make_float2(acc[mf][nf][h * 2 + 0] + bias,
                                       acc[mf][nf][h * 2 + 1] + bias);
                float* dst = (row < 16) ? &g_Q[((size_t)b * KD + row) * M_ + col]
                                        : &g_P[((size_t)b * UK + row - 16) * M_ + col];
                *(float2*)dst = v;
            }
        }
    }
}

// ---------------- k4: row softmax; fp32 logits -> fp16 weights ----------------
__global__ __launch_bounds__(256) void k4_softmax() {
    __shared__ float red[8];
    const int rid = blockIdx.x, tid = threadIdx.x;
    const int lane = tid & 31, warp = tid >> 5;
    const float4* p4 = (const float4*)(g_P + (size_t)rid * M_);

    float4 v[4];
    float lmax = -3.0e38f;
#pragma unroll
    for (int i = 0; i < 4; i++) {
        v[i] = p4[tid + i * 256];
        lmax = fmaxf(lmax, fmaxf(fmaxf(v[i].x, v[i].y), fmaxf(v[i].z, v[i].w)));
    }
#pragma unroll
    for (int o = 16; o > 0; o >>= 1)
        lmax = fmaxf(lmax, __shfl_xor_sync(0xffffffffu, lmax, o));
    if (lane == 0) red[warp] = lmax;
    __syncthreads();
    float mx = red[0];
#pragma unroll
    for (int w = 1; w < 8; w++) mx = fmaxf(mx, red[w]);
    __syncthreads();

    float lsum = 0.f;
#pragma unroll
    for (int i = 0; i < 4; i++) {
        v[i].x = __expf(v[i].x - mx); v[i].y = __expf(v[i].y - mx);
        v[i].z = __expf(v[i].z - mx); v[i].w = __expf(v[i].w - mx);
        lsum += v[i].x + v[i].y + v[i].z + v[i].w;
    }
#pragma unroll
    for (int o = 16; o > 0; o >>= 1)
        lsum += __shfl_xor_sync(0xffffffffu, lsum, o);
    if (lane == 0) red[warp] = lsum;
    __syncthreads();
    float tot = red[0];
#pragma unroll
    for (int w = 1; w < 8; w++) tot += red[w];
    const float inv = 1.0f / tot;

    uint2* out = (uint2*)(g_Ph + (size_t)rid * M_);
#pragma unroll
    for (int i = 0; i < 4; i++) {
        out[tid + i * 256] = make_uint2(
            h2bits(__floats2half2_rn(v[i].x * inv, v[i].y * inv)),
            h2bits(__floats2half2_rn(v[i].z * inv, v[i].w * inv)));
    }
}

// ---------------- k5: T = softmax(K) x^T (fp16 mma) ----------------
// grid (2 n-tiles of 128, 8 kz-splits of 512, B_). NC=8 chunks of 64 m.
__global__ __launch_bounds__(256, 2) void k5_T() {
    extern __shared__ float smem[];
    const int nt = blockIdx.x, kz = blockIdx.y, b = blockIdx.z;
    const int tid = threadIdx.x, lane = tid & 31, warp = tid >> 5;
    const int wm = warp >> 2, wn = warp & 3;
    const __half* Ag = g_Ph + (size_t)b * UK * M_ + kz * 512;
    const __half* Bg = g_xh + (size_t)b * C_ * M_ + (size_t)(nt * 128) * M_ + kz * 512;
    const unsigned s0 = sptr(smem);
    const int NC = 8;

    float acc[2][4][4];
#pragma unroll
    for (int i = 0; i < 2; i++)
#pragma unroll
        for (int j = 0; j < 4; j++)
#pragma unroll
            for (int r = 0; r < 4; r++) acc[i][j][r] = 0.f;

    auto stage = [&](int c, int s) {
        unsigned ab = s0 + s * 24576u;
        unsigned bb = ab + 8192u;
        const __half* As = Ag + c * 64;
        const __half* Bs = Bg + c * 64;
#pragma unroll
        for (int it = 0; it < 2; it++) {
            int id = tid + it * 256;
            int r = id >> 3, ch = id & 7;
            cpa16(ab + r * 128 + ((ch ^ (r & 7)) << 4), As + (size_t)r * M_ + ch * 8);
        }
#pragma unroll
        for (int it = 0; it < 4; it++) {
            int id = tid + it * 256;
            int r = id >> 3, ch = id & 7;
            cpa16(bb + r * 128 + ((ch ^ (r & 7)) << 4), Bs + (size_t)r * M_ + ch * 8);
        }
    };

    stage(0, 0); cpcommit();
    stage(1, 1); cpcommit();

    for (int i = 0; i < NC; i++) {
        cpwait1(); __syncthreads();
        int s = i % 3;
        unsigned ab = s0 + s * 24576u, bb = ab + 8192u;
#pragma unroll
        for (int kb = 0; kb < 4; kb++) {
            unsigned af[2][4], bf[2][4];
#pragma unroll
            for (int mf = 0; mf < 2; mf++)
                ldsm4(af[mf], a_addr(ab, wm * 32 + mf * 16, kb, lane));
#pragma unroll
            for (int pq = 0; pq < 2; pq++)
                ldsm4(bf[pq], b_addr(bb, wn * 32 + pq * 16, kb, lane));
#pragma unroll
            for (int mf = 0; mf < 2; mf++)
#pragma unroll
                for (int pq = 0; pq < 2; pq++) {
                    mma16h(acc[mf][pq * 2 + 0], af[mf], &bf[pq][0]);
                    mma16h(acc[mf][pq * 2 + 1], af[mf], &bf[pq][2]);
                }
        }
        if (i + 2 < NC) stage(i + 2, (i + 2) % 3);
        cpcommit();
    }

    const int g = lane >> 2, t = lane & 3;
#pragma unroll
    for (int mf = 0; mf < 2; mf++) {
        int row = wm * 32 + mf * 16 + g;
#pragma unroll
        for (int nf = 0; nf < 4; nf++) {
            int col = nt * 128 + wn * 32 + nf * 8 + 2 * t;
            atomicAdd(&g_T[((size_t)b * UK + row) * C_ + col],         acc[mf][nf][0]);
            atomicAdd(&g_T[((size_t)b * UK + row) * C_ + col + 1],     acc[mf][nf][1]);
            atomicAdd(&g_T[((size_t)b * UK + row + 8) * C_ + col],     acc[mf][nf][2]);
            atomicAdd(&g_T[((size_t)b * UK + row + 8) * C_ + col + 1], acc[mf][nf][3]);
        }
    }
}

// ---------------- k6: context ----------------
__global__ __launch_bounds__(256) void k6_ctx() {
    __shared__ float sT[16][C_];
    __shared__ float sW[VD][17];
    const int u = blockIdx.x, b = blockIdx.y, tid = threadIdx.x;
    const float* Tsrc = g_T + ((size_t)b * UK + u * 16) * C_;
#pragma unroll
    for (int i = 0; i < 16; i++) sT[i][tid] = Tsrc[i * C_ + tid];

    float acc[16];
#pragma unroll
    for (int i = 0; i < 16; i++) acc[i] = 0.f;
    const float* Wsrc = g_WvEff + (size_t)u * VD * C_;
    const int lr0 = tid >> 4, lc0 = tid & 15;

    for (int c0 = 0; c0 < C_; c0 += 16) {
        __syncthreads();
#pragma unroll
        for (int i = 0; i < 16; i++) {
            int r = lr0 + i * 16;
            sW[r][lc0] = Wsrc[r * C_ + c0 + lc0];
        }
        __syncthreads();
#pragma unroll
        for (int cc = 0; cc < 16; cc++) {
            float wv = sW[tid][cc];
#pragma unroll
            for (int kk = 0; kk < 16; kk++)
                acc[kk] += sT[kk][c0 + cc] * wv;
        }
    }
#pragma unroll
    for (int kk = 0; kk < 16; kk++)
        atomicAdd(&g_ctx[((size_t)b * KD + kk) * VD + tid], acc[kk]);
}

// ---------------- k7: y = Q^T ctx ----------------
__global__ __launch_bounds__(256) void k7_y(float* __restrict__ y) {
    __shared__ float sctx[16][VD];
    __shared__ float sQ[16][257];
    const int mt = blockIdx.x, b = blockIdx.y, tid = threadIdx.x;
    const float cbv = g_cb[tid];
#pragma unroll
    for (int i = 0; i < 16; i++)
        sctx[i][tid] = g_ctx[((size_t)b * KD + i) * VD + tid] + cbv;
    const float* Qb = g_Q + (size_t)b * KD * M_ + mt * 256;
#pragma unroll
    for (int i = 0; i < 16; i++) sQ[i][tid] = Qb[(size_t)i * M_ + tid];
    __syncthreads();

    float q[16];
#pragma unroll
    for (int i = 0; i < 16; i++) q[i] = sQ[i][tid];
    float* yb = y + (size_t)b * VD * M_ + mt * 256 + tid;
    for (int v = 0; v < VD; v += 4) {
        float4 a = make_float4(0.f, 0.f, 0.f, 0.f);
#pragma unroll
        for (int kk = 0; kk < 16; kk++) {
            const float4 cv = *(const float4*)&sctx[kk][v];
            a.x += q[kk] * cv.x; a.y += q[kk] * cv.y;
            a.z += q[kk] * cv.z; a.w += q[kk] * cv.w;
        }
        yb[(size_t)(v + 0) * M_] = a.x;
        yb[(size_t)(v + 1) * M_] = a.y;
        yb[(size_t)(v + 2) * M_] = a.z;
        yb[(size_t)(v + 3) * M_] = a.w;
    }
}

// ---------------- launch ----------------
extern "C" void kernel_launch(void* const* d_in, const int* in_sizes, int n_in,
                              void* d_out, int out_size) {
    const float* x   = (const float*)d_in[0];
    const float* Wq  = (const float*)d_in[1];
    const float* bq  = (const float*)d_in[2];
    const float* Wk  = (const float*)d_in[3];
    const float* bk  = (const float*)d_in[4];
    const float* Wv  = (const float*)d_in[5];
    const float* bv  = (const float*)d_in[6];
    const float* gq  = (const float*)d_in[7];
    const float* btq = (const float*)d_in[8];
    const float* gv  = (const float*)d_in[9];
    const float* btv = (const float*)d_in[10];
    float* y = (float*)d_out;

    cudaFuncSetAttribute(k1_gram, cudaFuncAttributeMaxDynamicSharedMemorySize, 3 * 32768);
    cudaFuncSetAttribute(k3_qk,   cudaFuncAttributeMaxDynamicSharedMemorySize, 3 * 26624);
    cudaFuncSetAttribute(k5_T,    cudaFuncAttributeMaxDynamicSharedMemorySize, 3 * 24576);

    kx_cvt<<<2048, 256>>>((const float4*)x);
    k1_gram<<<dim3(3, B_, 4), 256, 3 * 32768>>>();
    k2a_qf<<<dim3(65, 8), 256>>>(Wq, Wv);
    k2b_fold<<<69, 256>>>(Wq, bq, Wk, bk, Wv, bv, gq, btq, gv, btv);
    k3_qk<<<dim3(32, B_), 256, 3 * 26624>>>();
    k4_softmax<<<B_ * UK, 256>>>();
    k5_T<<<dim3(2, 8, B_), 256, 3 * 24576>>>();
    k6_ctx<<<dim3(UD, B_), 256>>>();
    k7_y<<<dim3(16, B_), 256>>>(y);
}